// round 7
// baseline (speedup 1.0000x reference)
#include <cuda_runtime.h>

#define Bb 32
#define Nn 1024
#define Hh 128
#define THREADS 256
#define WARPS 8
#define RPT 4
#define ROWS_PER_BLOCK (WARPS * RPT)  // 32
#define GRIDX (Nn / ROWS_PER_BLOCK)   // 32

__device__ float g_prm[9];     // u0..2, au, v0..2, av, kd (pre-scaled by log2 e)
__device__ int   g_mask_byte;
__device__ int   g_cnt[Bb];    // per-batch tickets (reset after use)

// precomputed, pharma-first reordered per batch
__device__ float2 g_AC[Bb * Nn];
__device__ float4 g_P[Bb * Nn];
__device__ float4 g_Q[Bb * Nn];
__device__ float  g_nn[Bb * Nn];   // MLP result (incl. lin2_b)
__device__ int    g_oidx[Bb * Nn]; // reordered pos -> original j
__device__ int    g_npj[Bb];

__device__ __forceinline__ float ex2f_(float x) {
    float y; asm("ex2.approx.ftz.f32 %0, %1;" : "=f"(y) : "f"(x)); return y;
}
__device__ __forceinline__ float sqrtf_(float x) {
    float y; asm("sqrt.approx.ftz.f32 %0, %1;" : "=f"(y) : "f"(x)); return y;
}
__device__ __forceinline__ bool mask_at(const void* m, int idx, int isByte) {
    if (isByte) return ((const unsigned char*)m)[idx] != 0;
    return ((const int*)m)[idx] != 0;
}

// One softmax term; loop AND diagonal correction use this -> bit-identical.
__device__ __forceinline__ float pair_term(float2 AC, float4 P, float cbw,
                                           float pxi, float pyi, float pzi,
                                           float sqi, float nrm) {
    float t = fmaf(P.z, pzi, P.w);
    t = fmaf(P.y, pyi, t);
    t = fmaf(P.x, pxi, t);
    float d2 = fmaxf(sqi + t, 1e-12f);
    float dist = sqrtf_(d2);
    float s = fmaf(nrm, AC.x, AC.y);
    s = fmaf(cbw, dist, s);
    return ex2f_(s);
}

// ---------------------------------------------------------------------------
__global__ __launch_bounds__(1024)
void setup_kernel(const unsigned int* __restrict__ nm,
                  const float* __restrict__ lin1_w,
                  const float* __restrict__ lin1_b,
                  const float* __restrict__ wp,
                  const float* __restrict__ bp,
                  const float* __restrict__ wd,
                  const float* __restrict__ wc) {
    int any = 0;
    for (int k = threadIdx.x; k < (Bb * Nn) / 4; k += 1024)
        if (nm[k] > 1u) any = 1;
    int r = __syncthreads_or(any);
    if (threadIdx.x == 0) g_mask_byte = r ? 1 : 0;

    if (threadIdx.x < 32) {
        const float L2E = 1.4426950408889634f;
        int lane = threadIdx.x;
        float u0 = 0.f, u1 = 0.f, u2 = 0.f, au = 0.f;
        float v0 = 0.f, v1 = 0.f, v2 = 0.f, av = 0.f, kd = 0.f;
        for (int h = lane; h < Hh; h += 32) {
            float w1h = wc[h];
            float w2h = wc[Hh + h];
            float a = lin1_w[h] * w1h;
            float c = lin1_b[h] * w1h;
            float wp0 = wp[h * 3 + 0], wp1 = wp[h * 3 + 1], wp2 = wp[h * 3 + 2];
            u0 = fmaf(a, wp0, u0); u1 = fmaf(a, wp1, u1); u2 = fmaf(a, wp2, u2);
            au = fmaf(a, bp[h], au);
            v0 = fmaf(c, wp0, v0); v1 = fmaf(c, wp1, v1); v2 = fmaf(c, wp2, v2);
            av = fmaf(c, bp[h], av);
            kd = fmaf(wd[h], w2h, kd);
        }
        #pragma unroll
        for (int o = 16; o > 0; o >>= 1) {
            u0 += __shfl_xor_sync(0xFFFFFFFFu, u0, o);
            u1 += __shfl_xor_sync(0xFFFFFFFFu, u1, o);
            u2 += __shfl_xor_sync(0xFFFFFFFFu, u2, o);
            au += __shfl_xor_sync(0xFFFFFFFFu, au, o);
            v0 += __shfl_xor_sync(0xFFFFFFFFu, v0, o);
            v1 += __shfl_xor_sync(0xFFFFFFFFu, v1, o);
            v2 += __shfl_xor_sync(0xFFFFFFFFu, v2, o);
            av += __shfl_xor_sync(0xFFFFFFFFu, av, o);
            kd += __shfl_xor_sync(0xFFFFFFFFu, kd, o);
        }
        if (lane == 0) {
            g_prm[0] = u0 * L2E; g_prm[1] = u1 * L2E; g_prm[2] = u2 * L2E; g_prm[3] = au * L2E;
            g_prm[4] = v0 * L2E; g_prm[5] = v1 * L2E; g_prm[6] = v2 * L2E; g_prm[7] = av * L2E;
            g_prm[8] = kd * L2E;
        }
    }
}

// ---------------------------------------------------------------------------
// Precompute: per batch, pharma-first reorder + j-data SoA + per-row MLP.
// grid (4, Bb): each block scans its whole batch, writes its quarter.
// ---------------------------------------------------------------------------
__global__ __launch_bounds__(THREADS)
void pre_kernel(const float* __restrict__ pos,
                const float* __restrict__ p,
                const void* __restrict__ pharma,
                const float* __restrict__ lin1_w,
                const float* __restrict__ lin1_b,
                const float* __restrict__ lin2_w,
                const float* __restrict__ lin2_b) {
    __shared__ int   s_chk[32];
    __shared__ int   s_npj;
    __shared__ float s_l1w[Hh], s_l1b[Hh], s_l2w[Hh];

    const int b = blockIdx.y;
    const int q = blockIdx.x;
    const int tid = threadIdx.x;
    const int w = tid >> 5;
    const int lane = tid & 31;
    const int isB = g_mask_byte;

    if (tid < Hh) {
        s_l1w[tid] = lin1_w[tid];
        s_l1b[tid] = lin1_b[tid];
        s_l2w[tid] = lin2_w[tid];
    }

    // pass 1: per-chunk pharma counts for the full batch
    #pragma unroll
    for (int k = 0; k < Nn / THREADS; k++) {
        int j = k * THREADS + tid;
        bool ph = mask_at(pharma, b * Nn + j, isB);
        unsigned m = __ballot_sync(0xFFFFFFFFu, ph);
        if (lane == 0) s_chk[k * WARPS + w] = __popc(m);
    }
    __syncthreads();
    if (tid < 32) {
        int v = s_chk[tid];
        int incl = v;
        #pragma unroll
        for (int o = 1; o < 32; o <<= 1) {
            int t = __shfl_up_sync(0xFFFFFFFFu, incl, o);
            if (lane >= o) incl += t;
        }
        s_chk[tid] = incl - v;
        if (tid == 31) s_npj = incl;
    }
    __syncthreads();
    const int npj = s_npj;

    const float u0 = g_prm[0], u1 = g_prm[1], u2 = g_prm[2], au = g_prm[3];
    const float v0 = g_prm[4], v1 = g_prm[5], v2 = g_prm[6], av = g_prm[7];
    const float kdL = g_prm[8];
    const float l2b = lin2_b[0];

    // pass 2: this block's quarter of j
    {
        int j = q * THREADS + tid;
        bool ph = mask_at(pharma, b * Nn + j, isB);
        unsigned m = __ballot_sync(0xFFFFFFFFu, ph);
        unsigned below = m & ((1u << lane) - 1u);
        int c = q * WARPS + w;
        int phOff = s_chk[c];
        int pos_;
        if (ph) pos_ = phOff + __popc(below);
        else    pos_ = npj + (c * 32 - phOff) + (lane - __popc(below));

        const float* posb = pos + (size_t)b * Nn * 3;
        const float* pb   = p   + (size_t)b * Nn * 3;
        float qx = posb[j * 3 + 0], qy = posb[j * 3 + 1], qz = posb[j * 3 + 2];
        float A = fmaf(qx, u0, fmaf(qy, u1, fmaf(qz, u2, au)));
        float C = fmaf(qx, v0, fmaf(qy, v1, fmaf(qz, v2, av)));
        float px = pb[j * 3 + 0], py = pb[j * 3 + 1], pz = pb[j * 3 + 2];
        float sq = fmaf(px, px, fmaf(py, py, pz * pz));

        int gp = b * Nn + pos_;
        g_AC[gp] = make_float2(A, C);
        g_P[gp]  = make_float4(-2.f * px, -2.f * py, -2.f * pz, sq);
        g_Q[gp]  = make_float4(qx, qy, qz, ph ? kdL : 0.f);
        g_oidx[gp] = j;

        // per-row MLP
        __syncthreads();  // s_l1w ready (also after scan sync above; keep ordering safe)
        float nrm = sqrtf(fmaf(qx, qx, fmaf(qy, qy, qz * qz)));
        float nn = 0.f;
        #pragma unroll 8
        for (int h = 0; h < Hh; h++) {
            float hid = fmaf(nrm, s_l1w[h], s_l1b[h]);
            nn = fmaf(fmaxf(hid, 0.f), s_l2w[h], nn);
        }
        g_nn[gp] = nn + l2b;
    }

    if (q == 0 && tid == 0) g_npj[b] = npj;
}

// ---------------------------------------------------------------------------
// Main kernel: rows are contiguous in reordered space. Preamble = pure copy.
// Register double-buffered j-tile loads.
// ---------------------------------------------------------------------------
__global__ __launch_bounds__(THREADS, 3)
void attn_kernel(const void* __restrict__ node_mask,
                 float* __restrict__ out) {
    __shared__ float2 s_AC[Nn];
    __shared__ float4 s_P[Nn];
    __shared__ float4 s_Q[Nn];
    __shared__ float  s_red[WARPS];
    __shared__ float  s_mean[3];
    __shared__ int    s_tk;

    const int b = blockIdx.y;
    const int tid = threadIdx.x;
    const int w = tid >> 5;
    const int lane = tid & 31;
    const int isB = g_mask_byte;

    // preamble: coalesced copy of precomputed batch data
    {
        const float4* gp = (const float4*)&g_P[b * Nn];
        const float4* gq = (const float4*)&g_Q[b * Nn];
        const float4* ga = (const float4*)&g_AC[b * Nn];
        float4* sp = (float4*)s_P;
        float4* sq = (float4*)s_Q;
        float4* sa = (float4*)s_AC;
        #pragma unroll
        for (int i = tid; i < Nn; i += THREADS) { sp[i] = gp[i]; sq[i] = gq[i]; }
        #pragma unroll
        for (int i = tid; i < Nn / 2; i += THREADS) sa[i] = ga[i];
    }
    const int npj = g_npj[b];
    __syncthreads();

    const int rb = blockIdx.x * ROWS_PER_BLOCK;
    const int base = w * RPT;
    const int p0 = rb + base;
    const int cls = (p0 + RPT <= npj) ? 0 : ((p0 >= npj) ? 2 : 1);
    const int njc = (npj + 31) >> 5;

    float pxi[RPT], pyi[RPT], pzi[RPT], sqi[RPT], nrm[RPT], rgf[RPT];
    float sum[RPT], cx[RPT], cy[RPT], cz[RPT];
    #pragma unroll
    for (int r = 0; r < RPT; r++) {
        int pi = p0 + r;
        float4 P = s_P[pi];
        pxi[r] = -0.5f * P.x; pyi[r] = -0.5f * P.y; pzi[r] = -0.5f * P.z;
        sqi[r] = P.w;
        float4 Q = s_Q[pi];
        nrm[r] = sqrtf(fmaf(Q.x, Q.x, fmaf(Q.y, Q.y, Q.z * Q.z)));
        rgf[r] = (pi < npj) ? 1.f : 0.f;
        sum[r] = 0.f; cx[r] = 0.f; cy[r] = 0.f; cz[r] = 0.f;
    }

    // double-buffered main loop
    {
        float2 AC = s_AC[lane];
        float4 P  = s_P[lane];
        float4 Q  = s_Q[lane];
        int jj = 0;
        if (cls != 2) {
            #pragma unroll 2
            for (; jj < njc; jj++) {
                int jn = ((jj + 1 < 32) ? jj + 1 : jj) * 32 + lane;
                float2 ACn = s_AC[jn];
                float4 Pn  = s_P[jn];
                float4 Qn  = s_Q[jn];
                if (cls == 0) {
                    #pragma unroll
                    for (int r = 0; r < RPT; r++) {
                        float e = pair_term(AC, P, Q.w, pxi[r], pyi[r], pzi[r], sqi[r], nrm[r]);
                        sum[r] += e;
                        cx[r] = fmaf(e, Q.x, cx[r]);
                        cy[r] = fmaf(e, Q.y, cy[r]);
                        cz[r] = fmaf(e, Q.z, cz[r]);
                    }
                } else {
                    #pragma unroll
                    for (int r = 0; r < RPT; r++) {
                        float cb = Q.w * rgf[r];
                        float e = pair_term(AC, P, cb, pxi[r], pyi[r], pzi[r], sqi[r], nrm[r]);
                        sum[r] += e;
                        cx[r] = fmaf(e, Q.x, cx[r]);
                        cy[r] = fmaf(e, Q.y, cy[r]);
                        cz[r] = fmaf(e, Q.z, cz[r]);
                    }
                }
                AC = ACn; P = Pn; Q = Qn;
            }
        }
        #pragma unroll 2
        for (; jj < Nn / 32; jj++) {
            int jn = ((jj + 1 < 32) ? jj + 1 : jj) * 32 + lane;
            float2 ACn = s_AC[jn];
            float4 Qn  = s_Q[jn];
            #pragma unroll
            for (int r = 0; r < RPT; r++) {
                float e = ex2f_(fmaf(nrm[r], AC.x, AC.y));
                sum[r] += e;
                cx[r] = fmaf(e, Q.x, cx[r]);
                cy[r] = fmaf(e, Q.y, cy[r]);
                cz[r] = fmaf(e, Q.z, cz[r]);
            }
            AC = ACn; Q = Qn;
        }
    }

    #pragma unroll
    for (int r = 0; r < RPT; r++) {
        #pragma unroll
        for (int o = 16; o > 0; o >>= 1) {
            sum[r] += __shfl_xor_sync(0xFFFFFFFFu, sum[r], o);
            cx[r]  += __shfl_xor_sync(0xFFFFFFFFu, cx[r], o);
            cy[r]  += __shfl_xor_sync(0xFFFFFFFFu, cy[r], o);
            cz[r]  += __shfl_xor_sync(0xFFFFFFFFu, cz[r], o);
        }
    }

    #pragma unroll
    for (int r = 0; r < RPT; r++) {
        if (lane == r) {
            int pi = p0 + r;
            float4 Q = s_Q[pi];
            float S = sum[r], X = cx[r], Y = cy[r], Z = cz[r];
            if (cls != 2) {
                // remove loop's j==i term, add dist-free term (bit-exact redo)
                float cbw = Q.w * rgf[r];
                float e_wrong = pair_term(s_AC[pi], s_P[pi], cbw,
                                          pxi[r], pyi[r], pzi[r], sqi[r], nrm[r]);
                float e_right = ex2f_(fmaf(nrm[r], s_AC[pi].x, s_AC[pi].y));
                float d = e_right - e_wrong;
                S += d; X = fmaf(d, Q.x, X); Y = fmaf(d, Q.y, Y); Z = fmaf(d, Q.z, Z);
            }
            int oi = g_oidx[b * Nn + pi];
            int gi = b * Nn + oi;
            float nn = g_nn[b * Nn + pi];
            float f = mask_at(node_mask, gi, isB)
                        ? nn / (S * (nrm[r] + 1e-5f)) : 0.f;
            out[gi * 3 + 0] = Q.x * X * f;
            out[gi * 3 + 1] = Q.y * Y * f;
            out[gi * 3 + 2] = Q.z * Z * f;
        }
    }

    // fused per-batch mean subtraction (last block of batch)
    __threadfence();
    __syncthreads();
    if (tid == 0) s_tk = atomicAdd(&g_cnt[b], 1);
    __syncthreads();
    if (s_tk == GRIDX - 1) {
        __threadfence();
        float ax = 0.f, ay = 0.f, az = 0.f;
        for (int n = tid; n < Nn; n += THREADS) {
            const float* o = out + ((size_t)b * Nn + n) * 3;
            ax += o[0]; ay += o[1]; az += o[2];
        }
        float* comps[3] = {&ax, &ay, &az};
        #pragma unroll
        for (int c = 0; c < 3; c++) {
            float v = *comps[c];
            #pragma unroll
            for (int o = 16; o > 0; o >>= 1) v += __shfl_xor_sync(0xFFFFFFFFu, v, o);
            if (lane == 0) s_red[w] = v;
            __syncthreads();
            if (tid == 0) {
                float t = 0.f;
                #pragma unroll
                for (int k = 0; k < WARPS; k++) t += s_red[k];
                s_mean[c] = t * (1.f / Nn);
            }
            __syncthreads();
        }
        float mx = s_mean[0], my = s_mean[1], mz = s_mean[2];
        for (int n = tid; n < Nn; n += THREADS) {
            float* o = out + ((size_t)b * Nn + n) * 3;
            o[0] -= mx; o[1] -= my; o[2] -= mz;
        }
        if (tid == 0) atomicExch(&g_cnt[b], 0);
    }
}

extern "C" void kernel_launch(void* const* d_in, const int* in_sizes, int n_in,
                              void* d_out, int out_size) {
    const float* pos       = (const float*)d_in[0];
    const void*  node_mask = d_in[1];
    const float* p         = (const float*)d_in[2];
    const void*  pharma    = d_in[3];
    const float* lin1_w    = (const float*)d_in[4];
    const float* lin1_b    = (const float*)d_in[5];
    const float* lin2_w    = (const float*)d_in[6];
    const float* lin2_b    = (const float*)d_in[7];
    const float* wp        = (const float*)d_in[8];
    const float* bp        = (const float*)d_in[9];
    const float* wd        = (const float*)d_in[10];
    const float* wc        = (const float*)d_in[12];

    setup_kernel<<<1, 1024>>>((const unsigned int*)node_mask,
                              lin1_w, lin1_b, wp, bp, wd, wc);

    dim3 pgrid(Nn / THREADS, Bb);   // (4, 32)
    pre_kernel<<<pgrid, THREADS>>>(pos, p, pharma, lin1_w, lin1_b, lin2_w, lin2_b);

    dim3 grid(GRIDX, Bb);
    attn_kernel<<<grid, THREADS>>>(node_mask, (float*)d_out);
}

// round 8
// speedup vs baseline: 1.1047x; 1.1047x over previous
#include <cuda_runtime.h>

#define Bb 32
#define Nn 1024
#define Hh 128
#define THREADS 256
#define WARPS 8
#define RPT 4
#define ROWS_PER_BLOCK (WARPS * RPT)  // 32
#define GRIDX (Nn / ROWS_PER_BLOCK)   // 32

__device__ int   g_cnt[Bb];    // per-batch tickets (reset after use)

// precomputed, pharma-first reordered per batch
__device__ float2 g_AC[Bb * Nn];
__device__ float4 g_P[Bb * Nn];
__device__ float4 g_Q[Bb * Nn];
__device__ float  g_nn[Bb * Nn];   // MLP result incl. lin2_b, gated by node_mask
__device__ int    g_oidx[Bb * Nn]; // reordered pos -> original j
__device__ int    g_npj[Bb];

__device__ __forceinline__ float ex2f_(float x) {
    float y; asm("ex2.approx.ftz.f32 %0, %1;" : "=f"(y) : "f"(x)); return y;
}
__device__ __forceinline__ float sqrtf_(float x) {
    float y; asm("sqrt.approx.ftz.f32 %0, %1;" : "=f"(y) : "f"(x)); return y;
}
__device__ __forceinline__ bool mask_at(const void* m, int idx, int isByte) {
    if (isByte) return ((const unsigned char*)m)[idx] != 0;
    return ((const int*)m)[idx] != 0;
}

// One softmax term; loop AND diagonal correction use this -> bit-identical.
__device__ __forceinline__ float pair_term(float2 AC, float4 P, float cbw,
                                           float pxi, float pyi, float pzi,
                                           float sqi, float nrm) {
    float t = fmaf(P.z, pzi, P.w);
    t = fmaf(P.y, pyi, t);
    t = fmaf(P.x, pxi, t);
    float d2 = fmaxf(sqi + t, 1e-12f);
    float dist = sqrtf_(d2);
    float s = fmaf(nrm, AC.x, AC.y);
    s = fmaf(cbw, dist, s);
    return ex2f_(s);
}

// ---------------------------------------------------------------------------
// Precompute: per batch, mask-dtype detection, 9-scalar collapse (redundant
// per block), pharma-first reorder + j-data SoA + gated per-row MLP.
// grid (4, Bb): each block scans its whole batch, writes its quarter.
// ---------------------------------------------------------------------------
__global__ __launch_bounds__(THREADS)
void pre_kernel(const float* __restrict__ pos,
                const void* __restrict__ node_mask,
                const float* __restrict__ p,
                const void* __restrict__ pharma,
                const float* __restrict__ lin1_w,
                const float* __restrict__ lin1_b,
                const float* __restrict__ lin2_w,
                const float* __restrict__ lin2_b,
                const float* __restrict__ wp,
                const float* __restrict__ bp,
                const float* __restrict__ wd,
                const float* __restrict__ wc) {
    __shared__ int   s_chk[32];
    __shared__ int   s_npj;
    __shared__ float s_l1w[Hh], s_l1b[Hh], s_l2w[Hh];
    __shared__ float s_prm[9];

    const int b = blockIdx.y;
    const int q = blockIdx.x;
    const int tid = threadIdx.x;
    const int w = tid >> 5;
    const int lane = tid & 31;

    if (tid < Hh) {
        s_l1w[tid] = lin1_w[tid];
        s_l1b[tid] = lin1_b[tid];
        s_l2w[tid] = lin2_w[tid];
    }

    // mask-dtype detection: 256 words suffice (P[miss] = 8^-256)
    int any = (tid < 256) && (((const unsigned int*)node_mask)[tid] > 1u);
    const int isB = __syncthreads_or(any) ? 1 : 0;

    // warp 0: collapse H into 9 scalars (redundant per block; trivial cost)
    if (w == 0) {
        const float L2E = 1.4426950408889634f;
        float u0 = 0.f, u1 = 0.f, u2 = 0.f, au = 0.f;
        float v0 = 0.f, v1 = 0.f, v2 = 0.f, av = 0.f, kd = 0.f;
        for (int h = lane; h < Hh; h += 32) {
            float w1h = wc[h];
            float w2h = wc[Hh + h];
            float a = lin1_w[h] * w1h;
            float c = lin1_b[h] * w1h;
            float wp0 = wp[h * 3 + 0], wp1 = wp[h * 3 + 1], wp2 = wp[h * 3 + 2];
            u0 = fmaf(a, wp0, u0); u1 = fmaf(a, wp1, u1); u2 = fmaf(a, wp2, u2);
            au = fmaf(a, bp[h], au);
            v0 = fmaf(c, wp0, v0); v1 = fmaf(c, wp1, v1); v2 = fmaf(c, wp2, v2);
            av = fmaf(c, bp[h], av);
            kd = fmaf(wd[h], w2h, kd);
        }
        #pragma unroll
        for (int o = 16; o > 0; o >>= 1) {
            u0 += __shfl_xor_sync(0xFFFFFFFFu, u0, o);
            u1 += __shfl_xor_sync(0xFFFFFFFFu, u1, o);
            u2 += __shfl_xor_sync(0xFFFFFFFFu, u2, o);
            au += __shfl_xor_sync(0xFFFFFFFFu, au, o);
            v0 += __shfl_xor_sync(0xFFFFFFFFu, v0, o);
            v1 += __shfl_xor_sync(0xFFFFFFFFu, v1, o);
            v2 += __shfl_xor_sync(0xFFFFFFFFu, v2, o);
            av += __shfl_xor_sync(0xFFFFFFFFu, av, o);
            kd += __shfl_xor_sync(0xFFFFFFFFu, kd, o);
        }
        if (lane == 0) {
            s_prm[0] = u0 * L2E; s_prm[1] = u1 * L2E; s_prm[2] = u2 * L2E; s_prm[3] = au * L2E;
            s_prm[4] = v0 * L2E; s_prm[5] = v1 * L2E; s_prm[6] = v2 * L2E; s_prm[7] = av * L2E;
            s_prm[8] = kd * L2E;
        }
    }

    // pass 1: per-chunk pharma counts for the full batch
    #pragma unroll
    for (int k = 0; k < Nn / THREADS; k++) {
        int j = k * THREADS + tid;
        bool ph = mask_at(pharma, b * Nn + j, isB);
        unsigned m = __ballot_sync(0xFFFFFFFFu, ph);
        if (lane == 0) s_chk[k * WARPS + w] = __popc(m);
    }
    __syncthreads();
    if (tid < 32) {
        int v = s_chk[tid];
        int incl = v;
        #pragma unroll
        for (int o = 1; o < 32; o <<= 1) {
            int t = __shfl_up_sync(0xFFFFFFFFu, incl, o);
            if (lane >= o) incl += t;
        }
        s_chk[tid] = incl - v;
        if (tid == 31) s_npj = incl;
    }
    __syncthreads();
    const int npj = s_npj;

    const float u0 = s_prm[0], u1 = s_prm[1], u2 = s_prm[2], au = s_prm[3];
    const float v0 = s_prm[4], v1 = s_prm[5], v2 = s_prm[6], av = s_prm[7];
    const float kdL = s_prm[8];
    const float l2b = lin2_b[0];

    // pass 2: this block's quarter of j
    {
        int j = q * THREADS + tid;
        bool ph = mask_at(pharma, b * Nn + j, isB);
        unsigned m = __ballot_sync(0xFFFFFFFFu, ph);
        unsigned below = m & ((1u << lane) - 1u);
        int c = q * WARPS + w;
        int phOff = s_chk[c];
        int pos_;
        if (ph) pos_ = phOff + __popc(below);
        else    pos_ = npj + (c * 32 - phOff) + (lane - __popc(below));

        const float* posb = pos + (size_t)b * Nn * 3;
        const float* pb   = p   + (size_t)b * Nn * 3;
        float qx = posb[j * 3 + 0], qy = posb[j * 3 + 1], qz = posb[j * 3 + 2];
        float A = fmaf(qx, u0, fmaf(qy, u1, fmaf(qz, u2, au)));
        float C = fmaf(qx, v0, fmaf(qy, v1, fmaf(qz, v2, av)));
        float px = pb[j * 3 + 0], py = pb[j * 3 + 1], pz = pb[j * 3 + 2];
        float sq = fmaf(px, px, fmaf(py, py, pz * pz));

        int gp = b * Nn + pos_;
        g_AC[gp] = make_float2(A, C);
        g_P[gp]  = make_float4(-2.f * px, -2.f * py, -2.f * pz, sq);
        g_Q[gp]  = make_float4(qx, qy, qz, ph ? kdL : 0.f);
        g_oidx[gp] = j;

        // per-row MLP, gated by node_mask (f becomes 0 automatically if masked)
        float nrm = sqrtf(fmaf(qx, qx, fmaf(qy, qy, qz * qz)));
        float nn = 0.f;
        #pragma unroll 8
        for (int h = 0; h < Hh; h++) {
            float hid = fmaf(nrm, s_l1w[h], s_l1b[h]);
            nn = fmaf(fmaxf(hid, 0.f), s_l2w[h], nn);
        }
        bool node = mask_at(node_mask, b * Nn + j, isB);
        g_nn[gp] = node ? (nn + l2b) : 0.f;
    }

    if (q == 0 && tid == 0) g_npj[b] = npj;
}

// ---------------------------------------------------------------------------
// Main kernel: rows contiguous in reordered space; preamble = pure copy;
// register double-buffered j-tile loads. No masks needed.
// ---------------------------------------------------------------------------
__global__ __launch_bounds__(THREADS, 3)
void attn_kernel(float* __restrict__ out) {
    __shared__ float2 s_AC[Nn];
    __shared__ float4 s_P[Nn];
    __shared__ float4 s_Q[Nn];
    __shared__ float  s_red[WARPS];
    __shared__ float  s_mean[3];
    __shared__ int    s_tk;

    const int b = blockIdx.y;
    const int tid = threadIdx.x;
    const int w = tid >> 5;
    const int lane = tid & 31;

    // preamble: coalesced copy of precomputed batch data
    {
        const float4* gp = (const float4*)&g_P[b * Nn];
        const float4* gq = (const float4*)&g_Q[b * Nn];
        const float4* ga = (const float4*)&g_AC[b * Nn];
        float4* sp = (float4*)s_P;
        float4* sq = (float4*)s_Q;
        float4* sa = (float4*)s_AC;
        #pragma unroll
        for (int i = tid; i < Nn; i += THREADS) { sp[i] = gp[i]; sq[i] = gq[i]; }
        #pragma unroll
        for (int i = tid; i < Nn / 2; i += THREADS) sa[i] = ga[i];
    }
    const int npj = g_npj[b];
    __syncthreads();

    const int rb = blockIdx.x * ROWS_PER_BLOCK;
    const int base = w * RPT;
    const int p0 = rb + base;
    const int cls = (p0 + RPT <= npj) ? 0 : ((p0 >= npj) ? 2 : 1);
    const int njc = (npj + 31) >> 5;

    float pxi[RPT], pyi[RPT], pzi[RPT], sqi[RPT], nrm[RPT], rgf[RPT];
    float sum[RPT], cx[RPT], cy[RPT], cz[RPT];
    #pragma unroll
    for (int r = 0; r < RPT; r++) {
        int pi = p0 + r;
        float4 P = s_P[pi];
        pxi[r] = -0.5f * P.x; pyi[r] = -0.5f * P.y; pzi[r] = -0.5f * P.z;
        sqi[r] = P.w;
        float4 Q = s_Q[pi];
        nrm[r] = sqrtf(fmaf(Q.x, Q.x, fmaf(Q.y, Q.y, Q.z * Q.z)));
        rgf[r] = (pi < npj) ? 1.f : 0.f;
        sum[r] = 0.f; cx[r] = 0.f; cy[r] = 0.f; cz[r] = 0.f;
    }

    // double-buffered main loop
    {
        float2 AC = s_AC[lane];
        float4 P  = s_P[lane];
        float4 Q  = s_Q[lane];
        int jj = 0;
        if (cls != 2) {
            #pragma unroll 2
            for (; jj < njc; jj++) {
                int jn = ((jj + 1 < 32) ? jj + 1 : jj) * 32 + lane;
                float2 ACn = s_AC[jn];
                float4 Pn  = s_P[jn];
                float4 Qn  = s_Q[jn];
                if (cls == 0) {
                    #pragma unroll
                    for (int r = 0; r < RPT; r++) {
                        float e = pair_term(AC, P, Q.w, pxi[r], pyi[r], pzi[r], sqi[r], nrm[r]);
                        sum[r] += e;
                        cx[r] = fmaf(e, Q.x, cx[r]);
                        cy[r] = fmaf(e, Q.y, cy[r]);
                        cz[r] = fmaf(e, Q.z, cz[r]);
                    }
                } else {
                    #pragma unroll
                    for (int r = 0; r < RPT; r++) {
                        float cb = Q.w * rgf[r];
                        float e = pair_term(AC, P, cb, pxi[r], pyi[r], pzi[r], sqi[r], nrm[r]);
                        sum[r] += e;
                        cx[r] = fmaf(e, Q.x, cx[r]);
                        cy[r] = fmaf(e, Q.y, cy[r]);
                        cz[r] = fmaf(e, Q.z, cz[r]);
                    }
                }
                AC = ACn; P = Pn; Q = Qn;
            }
        }
        #pragma unroll 2
        for (; jj < Nn / 32; jj++) {
            int jn = ((jj + 1 < 32) ? jj + 1 : jj) * 32 + lane;
            float2 ACn = s_AC[jn];
            float4 Qn  = s_Q[jn];
            #pragma unroll
            for (int r = 0; r < RPT; r++) {
                float e = ex2f_(fmaf(nrm[r], AC.x, AC.y));
                sum[r] += e;
                cx[r] = fmaf(e, Q.x, cx[r]);
                cy[r] = fmaf(e, Q.y, cy[r]);
                cz[r] = fmaf(e, Q.z, cz[r]);
            }
            AC = ACn; Q = Qn;
        }
    }

    #pragma unroll
    for (int r = 0; r < RPT; r++) {
        #pragma unroll
        for (int o = 16; o > 0; o >>= 1) {
            sum[r] += __shfl_xor_sync(0xFFFFFFFFu, sum[r], o);
            cx[r]  += __shfl_xor_sync(0xFFFFFFFFu, cx[r], o);
            cy[r]  += __shfl_xor_sync(0xFFFFFFFFu, cy[r], o);
            cz[r]  += __shfl_xor_sync(0xFFFFFFFFu, cz[r], o);
        }
    }

    #pragma unroll
    for (int r = 0; r < RPT; r++) {
        if (lane == r) {
            int pi = p0 + r;
            float4 Q = s_Q[pi];
            float S = sum[r], X = cx[r], Y = cy[r], Z = cz[r];
            if (cls != 2) {
                // remove loop's j==i term, add dist-free term (bit-exact redo)
                float cbw = Q.w * rgf[r];
                float e_wrong = pair_term(s_AC[pi], s_P[pi], cbw,
                                          pxi[r], pyi[r], pzi[r], sqi[r], nrm[r]);
                float e_right = ex2f_(fmaf(nrm[r], s_AC[pi].x, s_AC[pi].y));
                float d = e_right - e_wrong;
                S += d; X = fmaf(d, Q.x, X); Y = fmaf(d, Q.y, Y); Z = fmaf(d, Q.z, Z);
            }
            int oi = g_oidx[b * Nn + pi];
            int gi = b * Nn + oi;
            float nn = g_nn[b * Nn + pi];     // already node-gated (0 if masked)
            float f = nn / (S * (nrm[r] + 1e-5f));
            out[gi * 3 + 0] = Q.x * X * f;
            out[gi * 3 + 1] = Q.y * Y * f;
            out[gi * 3 + 2] = Q.z * Z * f;
        }
    }

    // fused per-batch mean subtraction (last block of batch)
    __threadfence();
    __syncthreads();
    if (tid == 0) s_tk = atomicAdd(&g_cnt[b], 1);
    __syncthreads();
    if (s_tk == GRIDX - 1) {
        __threadfence();
        float ax = 0.f, ay = 0.f, az = 0.f;
        for (int n = tid; n < Nn; n += THREADS) {
            const float* o = out + ((size_t)b * Nn + n) * 3;
            ax += o[0]; ay += o[1]; az += o[2];
        }
        float* comps[3] = {&ax, &ay, &az};
        #pragma unroll
        for (int c = 0; c < 3; c++) {
            float v = *comps[c];
            #pragma unroll
            for (int o = 16; o > 0; o >>= 1) v += __shfl_xor_sync(0xFFFFFFFFu, v, o);
            if (lane == 0) s_red[w] = v;
            __syncthreads();
            if (tid == 0) {
                float t = 0.f;
                #pragma unroll
                for (int k = 0; k < WARPS; k++) t += s_red[k];
                s_mean[c] = t * (1.f / Nn);
            }
            __syncthreads();
        }
        float mx = s_mean[0], my = s_mean[1], mz = s_mean[2];
        for (int n = tid; n < Nn; n += THREADS) {
            float* o = out + ((size_t)b * Nn + n) * 3;
            o[0] -= mx; o[1] -= my; o[2] -= mz;
        }
        if (tid == 0) atomicExch(&g_cnt[b], 0);
    }
}

extern "C" void kernel_launch(void* const* d_in, const int* in_sizes, int n_in,
                              void* d_out, int out_size) {
    const float* pos       = (const float*)d_in[0];
    const void*  node_mask = d_in[1];
    const float* p         = (const float*)d_in[2];
    const void*  pharma    = d_in[3];
    const float* lin1_w    = (const float*)d_in[4];
    const float* lin1_b    = (const float*)d_in[5];
    const float* lin2_w    = (const float*)d_in[6];
    const float* lin2_b    = (const float*)d_in[7];
    const float* wp        = (const float*)d_in[8];
    const float* bp        = (const float*)d_in[9];
    const float* wd        = (const float*)d_in[10];
    const float* wc        = (const float*)d_in[12];

    dim3 pgrid(Nn / THREADS, Bb);   // (4, 32)
    pre_kernel<<<pgrid, THREADS>>>(pos, node_mask, p, pharma,
                                   lin1_w, lin1_b, lin2_w, lin2_b,
                                   wp, bp, wd, wc);

    dim3 grid(GRIDX, Bb);
    attn_kernel<<<grid, THREADS>>>((float*)d_out);
}

// round 9
// speedup vs baseline: 1.1766x; 1.0651x over previous
#include <cuda_runtime.h>

#define Bb 32
#define Nn 1024
#define Hh 128
#define THREADS 256
#define WARPS 8
#define RPT 4
#define ROWS_PER_BLOCK (WARPS * RPT)  // 32
#define GRIDX (Nn / ROWS_PER_BLOCK)   // 32

__device__ int   g_cnt[Bb];    // per-batch tickets (reset after use)

// precomputed, pharma-first reordered per batch
__device__ float2 g_AC[Bb * Nn];
__device__ float4 g_P[Bb * Nn];
__device__ float4 g_Q[Bb * Nn];
__device__ float  g_nn[Bb * Nn];   // MLP result incl. lin2_b, gated by node_mask
__device__ int    g_oidx[Bb * Nn]; // reordered pos -> original j
__device__ int    g_npj[Bb];

__device__ __forceinline__ float ex2f_(float x) {
    float y; asm("ex2.approx.ftz.f32 %0, %1;" : "=f"(y) : "f"(x)); return y;
}
__device__ __forceinline__ float sqrtf_(float x) {
    float y; asm("sqrt.approx.ftz.f32 %0, %1;" : "=f"(y) : "f"(x)); return y;
}
__device__ __forceinline__ bool mask_at(const void* m, int idx, int isByte) {
    if (isByte) return ((const unsigned char*)m)[idx] != 0;
    return ((const int*)m)[idx] != 0;
}

// One softmax term; loop AND diagonal correction use this -> bit-identical.
__device__ __forceinline__ float pair_term(float2 AC, float4 P, float cbw,
                                           float pxi, float pyi, float pzi,
                                           float sqi, float nrm) {
    float t = fmaf(P.z, pzi, P.w);
    t = fmaf(P.y, pyi, t);
    t = fmaf(P.x, pxi, t);
    float d2 = fmaxf(sqi + t, 1e-12f);
    float dist = sqrtf_(d2);
    float s = fmaf(nrm, AC.x, AC.y);
    s = fmaf(cbw, dist, s);
    return ex2f_(s);
}

// ---------------------------------------------------------------------------
// Precompute: mask-dtype detection, 9-scalar collapse (redundant per block),
// pharma-first reorder + j-data SoA + gated per-row MLP.
// grid (4, Bb): each block scans its whole batch, writes its quarter.
// ---------------------------------------------------------------------------
__global__ __launch_bounds__(THREADS)
void pre_kernel(const float* __restrict__ pos,
                const void* __restrict__ node_mask,
                const float* __restrict__ p,
                const void* __restrict__ pharma,
                const float* __restrict__ lin1_w,
                const float* __restrict__ lin1_b,
                const float* __restrict__ lin2_w,
                const float* __restrict__ lin2_b,
                const float* __restrict__ wp,
                const float* __restrict__ bp,
                const float* __restrict__ wd,
                const float* __restrict__ wc) {
    __shared__ int   s_chk[32];
    __shared__ int   s_npj;
    __shared__ float s_l1w[Hh], s_l1b[Hh], s_l2w[Hh];
    __shared__ float s_prm[9];

    const int b = blockIdx.y;
    const int q = blockIdx.x;
    const int tid = threadIdx.x;
    const int w = tid >> 5;
    const int lane = tid & 31;

    if (tid < Hh) {
        s_l1w[tid] = lin1_w[tid];
        s_l1b[tid] = lin1_b[tid];
        s_l2w[tid] = lin2_w[tid];
    }

    // mask-dtype detection: 256 words suffice (P[miss] = 8^-256)
    int any = (tid < 256) && (((const unsigned int*)node_mask)[tid] > 1u);
    const int isB = __syncthreads_or(any) ? 1 : 0;

    // warp 0: collapse H into 9 scalars (redundant per block; trivial cost)
    if (w == 0) {
        const float L2E = 1.4426950408889634f;
        float u0 = 0.f, u1 = 0.f, u2 = 0.f, au = 0.f;
        float v0 = 0.f, v1 = 0.f, v2 = 0.f, av = 0.f, kd = 0.f;
        for (int h = lane; h < Hh; h += 32) {
            float w1h = wc[h];
            float w2h = wc[Hh + h];
            float a = lin1_w[h] * w1h;
            float c = lin1_b[h] * w1h;
            float wp0 = wp[h * 3 + 0], wp1 = wp[h * 3 + 1], wp2 = wp[h * 3 + 2];
            u0 = fmaf(a, wp0, u0); u1 = fmaf(a, wp1, u1); u2 = fmaf(a, wp2, u2);
            au = fmaf(a, bp[h], au);
            v0 = fmaf(c, wp0, v0); v1 = fmaf(c, wp1, v1); v2 = fmaf(c, wp2, v2);
            av = fmaf(c, bp[h], av);
            kd = fmaf(wd[h], w2h, kd);
        }
        #pragma unroll
        for (int o = 16; o > 0; o >>= 1) {
            u0 += __shfl_xor_sync(0xFFFFFFFFu, u0, o);
            u1 += __shfl_xor_sync(0xFFFFFFFFu, u1, o);
            u2 += __shfl_xor_sync(0xFFFFFFFFu, u2, o);
            au += __shfl_xor_sync(0xFFFFFFFFu, au, o);
            v0 += __shfl_xor_sync(0xFFFFFFFFu, v0, o);
            v1 += __shfl_xor_sync(0xFFFFFFFFu, v1, o);
            v2 += __shfl_xor_sync(0xFFFFFFFFu, v2, o);
            av += __shfl_xor_sync(0xFFFFFFFFu, av, o);
            kd += __shfl_xor_sync(0xFFFFFFFFu, kd, o);
        }
        if (lane == 0) {
            s_prm[0] = u0 * L2E; s_prm[1] = u1 * L2E; s_prm[2] = u2 * L2E; s_prm[3] = au * L2E;
            s_prm[4] = v0 * L2E; s_prm[5] = v1 * L2E; s_prm[6] = v2 * L2E; s_prm[7] = av * L2E;
            s_prm[8] = kd * L2E;
        }
    }

    // pass 1: per-chunk pharma counts for the full batch
    #pragma unroll
    for (int k = 0; k < Nn / THREADS; k++) {
        int j = k * THREADS + tid;
        bool ph = mask_at(pharma, b * Nn + j, isB);
        unsigned m = __ballot_sync(0xFFFFFFFFu, ph);
        if (lane == 0) s_chk[k * WARPS + w] = __popc(m);
    }
    __syncthreads();
    if (tid < 32) {
        int v = s_chk[tid];
        int incl = v;
        #pragma unroll
        for (int o = 1; o < 32; o <<= 1) {
            int t = __shfl_up_sync(0xFFFFFFFFu, incl, o);
            if (lane >= o) incl += t;
        }
        s_chk[tid] = incl - v;
        if (tid == 31) s_npj = incl;
    }
    __syncthreads();
    const int npj = s_npj;

    const float u0 = s_prm[0], u1 = s_prm[1], u2 = s_prm[2], au = s_prm[3];
    const float v0 = s_prm[4], v1 = s_prm[5], v2 = s_prm[6], av = s_prm[7];
    const float kdL = s_prm[8];
    const float l2b = lin2_b[0];

    // pass 2: this block's quarter of j
    {
        int j = q * THREADS + tid;
        bool ph = mask_at(pharma, b * Nn + j, isB);
        unsigned m = __ballot_sync(0xFFFFFFFFu, ph);
        unsigned below = m & ((1u << lane) - 1u);
        int c = q * WARPS + w;
        int phOff = s_chk[c];
        int pos_;
        if (ph) pos_ = phOff + __popc(below);
        else    pos_ = npj + (c * 32 - phOff) + (lane - __popc(below));

        const float* posb = pos + (size_t)b * Nn * 3;
        const float* pb   = p   + (size_t)b * Nn * 3;
        float qx = posb[j * 3 + 0], qy = posb[j * 3 + 1], qz = posb[j * 3 + 2];
        float A = fmaf(qx, u0, fmaf(qy, u1, fmaf(qz, u2, au)));
        float C = fmaf(qx, v0, fmaf(qy, v1, fmaf(qz, v2, av)));
        float px = pb[j * 3 + 0], py = pb[j * 3 + 1], pz = pb[j * 3 + 2];
        float sq = fmaf(px, px, fmaf(py, py, pz * pz));

        int gp = b * Nn + pos_;
        g_AC[gp] = make_float2(A, C);
        g_P[gp]  = make_float4(-2.f * px, -2.f * py, -2.f * pz, sq);
        g_Q[gp]  = make_float4(qx, qy, qz, ph ? kdL : 0.f);
        g_oidx[gp] = j;

        // per-row MLP, gated by node_mask (f becomes 0 automatically if masked)
        float nrm = sqrtf(fmaf(qx, qx, fmaf(qy, qy, qz * qz)));
        float nn = 0.f;
        #pragma unroll 8
        for (int h = 0; h < Hh; h++) {
            float hid = fmaf(nrm, s_l1w[h], s_l1b[h]);
            nn = fmaf(fmaxf(hid, 0.f), s_l2w[h], nn);
        }
        bool node = mask_at(node_mask, b * Nn + j, isB);
        g_nn[gp] = node ? (nn + l2b) : 0.f;
    }

    if (q == 0 && tid == 0) g_npj[b] = npj;
}

// ---------------------------------------------------------------------------
// Main kernel: rows contiguous in reordered space; preamble = pure copy;
// direct indexed LDS with unroll 4 (ptxas software-pipelines the loads).
// ---------------------------------------------------------------------------
__global__ __launch_bounds__(THREADS, 3)
void attn_kernel(float* __restrict__ out) {
    __shared__ float2 s_AC[Nn];
    __shared__ float4 s_P[Nn];
    __shared__ float4 s_Q[Nn];
    __shared__ float  s_red[WARPS];
    __shared__ float  s_mean[3];
    __shared__ int    s_tk;

    const int b = blockIdx.y;
    const int tid = threadIdx.x;
    const int w = tid >> 5;
    const int lane = tid & 31;

    // preamble: coalesced copy of precomputed batch data
    {
        const float4* gp = (const float4*)&g_P[b * Nn];
        const float4* gq = (const float4*)&g_Q[b * Nn];
        const float4* ga = (const float4*)&g_AC[b * Nn];
        float4* sp = (float4*)s_P;
        float4* sq = (float4*)s_Q;
        float4* sa = (float4*)s_AC;
        #pragma unroll
        for (int i = tid; i < Nn; i += THREADS) { sp[i] = gp[i]; sq[i] = gq[i]; }
        #pragma unroll
        for (int i = tid; i < Nn / 2; i += THREADS) sa[i] = ga[i];
    }
    const int npj = g_npj[b];
    __syncthreads();

    const int rb = blockIdx.x * ROWS_PER_BLOCK;
    const int base = w * RPT;
    const int p0 = rb + base;
    const int cls = (p0 + RPT <= npj) ? 0 : ((p0 >= npj) ? 2 : 1);
    const int njc = (npj + 31) >> 5;

    float pxi[RPT], pyi[RPT], pzi[RPT], sqi[RPT], nrm[RPT], rgf[RPT];
    float sum[RPT], cx[RPT], cy[RPT], cz[RPT];
    #pragma unroll
    for (int r = 0; r < RPT; r++) {
        int pi = p0 + r;
        float4 P = s_P[pi];
        pxi[r] = -0.5f * P.x; pyi[r] = -0.5f * P.y; pzi[r] = -0.5f * P.z;
        sqi[r] = P.w;
        float4 Q = s_Q[pi];
        nrm[r] = sqrtf(fmaf(Q.x, Q.x, fmaf(Q.y, Q.y, Q.z * Q.z)));
        rgf[r] = (pi < npj) ? 1.f : 0.f;
        sum[r] = 0.f; cx[r] = 0.f; cy[r] = 0.f; cz[r] = 0.f;
    }

    int jj = 0;
    if (cls == 0) {
        #pragma unroll 4
        for (; jj < njc; jj++) {          // distance segment
            const int j = jj * 32 + lane;
            const float2 AC = s_AC[j];
            const float4 P  = s_P[j];
            const float4 Q  = s_Q[j];
            #pragma unroll
            for (int r = 0; r < RPT; r++) {
                float e = pair_term(AC, P, Q.w, pxi[r], pyi[r], pzi[r], sqi[r], nrm[r]);
                sum[r] += e;
                cx[r] = fmaf(e, Q.x, cx[r]);
                cy[r] = fmaf(e, Q.y, cy[r]);
                cz[r] = fmaf(e, Q.z, cz[r]);
            }
        }
    } else if (cls == 1) {
        #pragma unroll 4
        for (; jj < njc; jj++) {          // mixed warp: gated distance
            const int j = jj * 32 + lane;
            const float2 AC = s_AC[j];
            const float4 P  = s_P[j];
            const float4 Q  = s_Q[j];
            #pragma unroll
            for (int r = 0; r < RPT; r++) {
                float cb = Q.w * rgf[r];
                float e = pair_term(AC, P, cb, pxi[r], pyi[r], pzi[r], sqi[r], nrm[r]);
                sum[r] += e;
                cx[r] = fmaf(e, Q.x, cx[r]);
                cy[r] = fmaf(e, Q.y, cy[r]);
                cz[r] = fmaf(e, Q.z, cz[r]);
            }
        }
    }
    #pragma unroll 4
    for (; jj < Nn / 32; jj++) {          // cheap segment
        const int j = jj * 32 + lane;
        const float2 AC = s_AC[j];
        const float4 Q  = s_Q[j];
        #pragma unroll
        for (int r = 0; r < RPT; r++) {
            float e = ex2f_(fmaf(nrm[r], AC.x, AC.y));
            sum[r] += e;
            cx[r] = fmaf(e, Q.x, cx[r]);
            cy[r] = fmaf(e, Q.y, cy[r]);
            cz[r] = fmaf(e, Q.z, cz[r]);
        }
    }

    #pragma unroll
    for (int r = 0; r < RPT; r++) {
        #pragma unroll
        for (int o = 16; o > 0; o >>= 1) {
            sum[r] += __shfl_xor_sync(0xFFFFFFFFu, sum[r], o);
            cx[r]  += __shfl_xor_sync(0xFFFFFFFFu, cx[r], o);
            cy[r]  += __shfl_xor_sync(0xFFFFFFFFu, cy[r], o);
            cz[r]  += __shfl_xor_sync(0xFFFFFFFFu, cz[r], o);
        }
    }

    #pragma unroll
    for (int r = 0; r < RPT; r++) {
        if (lane == r) {
            int pi = p0 + r;
            float4 Q = s_Q[pi];
            float S = sum[r], X = cx[r], Y = cy[r], Z = cz[r];
            if (cls != 2) {
                // remove loop's j==i term, add dist-free term (bit-exact redo)
                float cbw = Q.w * rgf[r];
                float e_wrong = pair_term(s_AC[pi], s_P[pi], cbw,
                                          pxi[r], pyi[r], pzi[r], sqi[r], nrm[r]);
                float e_right = ex2f_(fmaf(nrm[r], s_AC[pi].x, s_AC[pi].y));
                float d = e_right - e_wrong;
                S += d; X = fmaf(d, Q.x, X); Y = fmaf(d, Q.y, Y); Z = fmaf(d, Q.z, Z);
            }
            int oi = g_oidx[b * Nn + pi];
            int gi = b * Nn + oi;
            float nn = g_nn[b * Nn + pi];     // already node-gated (0 if masked)
            float f = nn / (S * (nrm[r] + 1e-5f));
            out[gi * 3 + 0] = Q.x * X * f;
            out[gi * 3 + 1] = Q.y * Y * f;
            out[gi * 3 + 2] = Q.z * Z * f;
        }
    }

    // fused per-batch mean subtraction (last block of batch)
    __threadfence();
    __syncthreads();
    if (tid == 0) s_tk = atomicAdd(&g_cnt[b], 1);
    __syncthreads();
    if (s_tk == GRIDX - 1) {
        __threadfence();
        float ax = 0.f, ay = 0.f, az = 0.f;
        for (int n = tid; n < Nn; n += THREADS) {
            const float* o = out + ((size_t)b * Nn + n) * 3;
            ax += o[0]; ay += o[1]; az += o[2];
        }
        float* comps[3] = {&ax, &ay, &az};
        #pragma unroll
        for (int c = 0; c < 3; c++) {
            float v = *comps[c];
            #pragma unroll
            for (int o = 16; o > 0; o >>= 1) v += __shfl_xor_sync(0xFFFFFFFFu, v, o);
            if (lane == 0) s_red[w] = v;
            __syncthreads();
            if (tid == 0) {
                float t = 0.f;
                #pragma unroll
                for (int k = 0; k < WARPS; k++) t += s_red[k];
                s_mean[c] = t * (1.f / Nn);
            }
            __syncthreads();
        }
        float mx = s_mean[0], my = s_mean[1], mz = s_mean[2];
        for (int n = tid; n < Nn; n += THREADS) {
            float* o = out + ((size_t)b * Nn + n) * 3;
            o[0] -= mx; o[1] -= my; o[2] -= mz;
        }
        if (tid == 0) atomicExch(&g_cnt[b], 0);
    }
}

extern "C" void kernel_launch(void* const* d_in, const int* in_sizes, int n_in,
                              void* d_out, int out_size) {
    const float* pos       = (const float*)d_in[0];
    const void*  node_mask = d_in[1];
    const float* p         = (const float*)d_in[2];
    const void*  pharma    = d_in[3];
    const float* lin1_w    = (const float*)d_in[4];
    const float* lin1_b    = (const float*)d_in[5];
    const float* lin2_w    = (const float*)d_in[6];
    const float* lin2_b    = (const float*)d_in[7];
    const float* wp        = (const float*)d_in[8];
    const float* bp        = (const float*)d_in[9];
    const float* wd        = (const float*)d_in[10];
    const float* wc        = (const float*)d_in[12];

    dim3 pgrid(Nn / THREADS, Bb);   // (4, 32)
    pre_kernel<<<pgrid, THREADS>>>(pos, node_mask, p, pharma,
                                   lin1_w, lin1_b, lin2_w, lin2_b,
                                   wp, bp, wd, wc);

    dim3 grid(GRIDX, Bb);
    attn_kernel<<<grid, THREADS>>>((float*)d_out);
}

// round 10
// speedup vs baseline: 1.1872x; 1.0090x over previous
#include <cuda_runtime.h>

#define Bb 32
#define Nn 1024
#define Hh 128
#define THREADS 256
#define WARPS 8
#define RPT 4
#define NPAIR 2
#define ROWS_PER_BLOCK (WARPS * RPT)  // 32
#define GRIDX (Nn / ROWS_PER_BLOCK)   // 32

__device__ int   g_cnt[Bb];    // per-batch tickets (reset after use)

// precomputed, pharma-first reordered per batch
__device__ float2 g_AC[Bb * Nn];
__device__ float4 g_P[Bb * Nn];
__device__ float4 g_Q[Bb * Nn];
__device__ float  g_nn[Bb * Nn];   // MLP result incl. lin2_b, gated by node_mask
__device__ int    g_oidx[Bb * Nn]; // reordered pos -> original j
__device__ int    g_npj[Bb];

typedef unsigned long long u64c;

__device__ __forceinline__ float ex2f_(float x) {
    float y; asm("ex2.approx.ftz.f32 %0, %1;" : "=f"(y) : "f"(x)); return y;
}
__device__ __forceinline__ float sqrtf_(float x) {
    float y; asm("sqrt.approx.ftz.f32 %0, %1;" : "=f"(y) : "f"(x)); return y;
}
__device__ __forceinline__ bool mask_at(const void* m, int idx, int isByte) {
    if (isByte) return ((const unsigned char*)m)[idx] != 0;
    return ((const int*)m)[idx] != 0;
}

// packed f32x2 helpers (FFMA2 path; identical .rn rounding to scalar FMA)
__device__ __forceinline__ u64c pk2(float lo, float hi) {
    u64c r; asm("mov.b64 %0, {%1, %2};" : "=l"(r) : "f"(lo), "f"(hi)); return r;
}
__device__ __forceinline__ void upk2(float& lo, float& hi, u64c v) {
    asm("mov.b64 {%0, %1}, %2;" : "=f"(lo), "=f"(hi) : "l"(v));
}
__device__ __forceinline__ u64c fma2_(u64c a, u64c b, u64c c) {
    u64c r; asm("fma.rn.f32x2 %0, %1, %2, %3;" : "=l"(r) : "l"(a), "l"(b), "l"(c)); return r;
}
__device__ __forceinline__ u64c add2_(u64c a, u64c b) {
    u64c r; asm("add.rn.f32x2 %0, %1, %2;" : "=l"(r) : "l"(a), "l"(b)); return r;
}
__device__ __forceinline__ u64c mul2_(u64c a, u64c b) {
    u64c r; asm("mul.rn.f32x2 %0, %1, %2;" : "=l"(r) : "l"(a), "l"(b)); return r;
}

// Scalar softmax term; matches the packed loop bit-exactly (used for the
// diagonal correction).
__device__ __forceinline__ float pair_term(float2 AC, float4 P, float cbw,
                                           float pxi, float pyi, float pzi,
                                           float sqi, float nrm) {
    float t = fmaf(P.z, pzi, P.w);
    t = fmaf(P.y, pyi, t);
    t = fmaf(P.x, pxi, t);
    float d2 = fmaxf(sqi + t, 1e-12f);
    float dist = sqrtf_(d2);
    float s = fmaf(nrm, AC.x, AC.y);
    s = fmaf(cbw, dist, s);
    return ex2f_(s);
}

// ---------------------------------------------------------------------------
// Precompute: mask-dtype detection, 9-scalar collapse (redundant per block),
// pharma-first reorder + j-data SoA + gated per-row MLP.
// ---------------------------------------------------------------------------
__global__ __launch_bounds__(THREADS)
void pre_kernel(const float* __restrict__ pos,
                const void* __restrict__ node_mask,
                const float* __restrict__ p,
                const void* __restrict__ pharma,
                const float* __restrict__ lin1_w,
                const float* __restrict__ lin1_b,
                const float* __restrict__ lin2_w,
                const float* __restrict__ lin2_b,
                const float* __restrict__ wp,
                const float* __restrict__ bp,
                const float* __restrict__ wd,
                const float* __restrict__ wc) {
    __shared__ int   s_chk[32];
    __shared__ int   s_npj;
    __shared__ float s_l1w[Hh], s_l1b[Hh], s_l2w[Hh];
    __shared__ float s_prm[9];

    const int b = blockIdx.y;
    const int q = blockIdx.x;
    const int tid = threadIdx.x;
    const int w = tid >> 5;
    const int lane = tid & 31;

    if (tid < Hh) {
        s_l1w[tid] = lin1_w[tid];
        s_l1b[tid] = lin1_b[tid];
        s_l2w[tid] = lin2_w[tid];
    }

    // mask-dtype detection: 256 words suffice (P[miss] = 8^-256)
    int any = (tid < 256) && (((const unsigned int*)node_mask)[tid] > 1u);
    const int isB = __syncthreads_or(any) ? 1 : 0;

    // warp 0: collapse H into 9 scalars (redundant per block; trivial cost)
    if (w == 0) {
        const float L2E = 1.4426950408889634f;
        float u0 = 0.f, u1 = 0.f, u2 = 0.f, au = 0.f;
        float v0 = 0.f, v1 = 0.f, v2 = 0.f, av = 0.f, kd = 0.f;
        for (int h = lane; h < Hh; h += 32) {
            float w1h = wc[h];
            float w2h = wc[Hh + h];
            float a = lin1_w[h] * w1h;
            float c = lin1_b[h] * w1h;
            float wp0 = wp[h * 3 + 0], wp1 = wp[h * 3 + 1], wp2 = wp[h * 3 + 2];
            u0 = fmaf(a, wp0, u0); u1 = fmaf(a, wp1, u1); u2 = fmaf(a, wp2, u2);
            au = fmaf(a, bp[h], au);
            v0 = fmaf(c, wp0, v0); v1 = fmaf(c, wp1, v1); v2 = fmaf(c, wp2, v2);
            av = fmaf(c, bp[h], av);
            kd = fmaf(wd[h], w2h, kd);
        }
        #pragma unroll
        for (int o = 16; o > 0; o >>= 1) {
            u0 += __shfl_xor_sync(0xFFFFFFFFu, u0, o);
            u1 += __shfl_xor_sync(0xFFFFFFFFu, u1, o);
            u2 += __shfl_xor_sync(0xFFFFFFFFu, u2, o);
            au += __shfl_xor_sync(0xFFFFFFFFu, au, o);
            v0 += __shfl_xor_sync(0xFFFFFFFFu, v0, o);
            v1 += __shfl_xor_sync(0xFFFFFFFFu, v1, o);
            v2 += __shfl_xor_sync(0xFFFFFFFFu, v2, o);
            av += __shfl_xor_sync(0xFFFFFFFFu, av, o);
            kd += __shfl_xor_sync(0xFFFFFFFFu, kd, o);
        }
        if (lane == 0) {
            s_prm[0] = u0 * L2E; s_prm[1] = u1 * L2E; s_prm[2] = u2 * L2E; s_prm[3] = au * L2E;
            s_prm[4] = v0 * L2E; s_prm[5] = v1 * L2E; s_prm[6] = v2 * L2E; s_prm[7] = av * L2E;
            s_prm[8] = kd * L2E;
        }
    }

    // pass 1: per-chunk pharma counts for the full batch
    #pragma unroll
    for (int k = 0; k < Nn / THREADS; k++) {
        int j = k * THREADS + tid;
        bool ph = mask_at(pharma, b * Nn + j, isB);
        unsigned m = __ballot_sync(0xFFFFFFFFu, ph);
        if (lane == 0) s_chk[k * WARPS + w] = __popc(m);
    }
    __syncthreads();
    if (tid < 32) {
        int v = s_chk[tid];
        int incl = v;
        #pragma unroll
        for (int o = 1; o < 32; o <<= 1) {
            int t = __shfl_up_sync(0xFFFFFFFFu, incl, o);
            if (lane >= o) incl += t;
        }
        s_chk[tid] = incl - v;
        if (tid == 31) s_npj = incl;
    }
    __syncthreads();
    const int npj = s_npj;

    const float u0 = s_prm[0], u1 = s_prm[1], u2 = s_prm[2], au = s_prm[3];
    const float v0 = s_prm[4], v1 = s_prm[5], v2 = s_prm[6], av = s_prm[7];
    const float kdL = s_prm[8];
    const float l2b = lin2_b[0];

    // pass 2: this block's quarter of j
    {
        int j = q * THREADS + tid;
        bool ph = mask_at(pharma, b * Nn + j, isB);
        unsigned m = __ballot_sync(0xFFFFFFFFu, ph);
        unsigned below = m & ((1u << lane) - 1u);
        int c = q * WARPS + w;
        int phOff = s_chk[c];
        int pos_;
        if (ph) pos_ = phOff + __popc(below);
        else    pos_ = npj + (c * 32 - phOff) + (lane - __popc(below));

        const float* posb = pos + (size_t)b * Nn * 3;
        const float* pb   = p   + (size_t)b * Nn * 3;
        float qx = posb[j * 3 + 0], qy = posb[j * 3 + 1], qz = posb[j * 3 + 2];
        float A = fmaf(qx, u0, fmaf(qy, u1, fmaf(qz, u2, au)));
        float C = fmaf(qx, v0, fmaf(qy, v1, fmaf(qz, v2, av)));
        float px = pb[j * 3 + 0], py = pb[j * 3 + 1], pz = pb[j * 3 + 2];
        float sq = fmaf(px, px, fmaf(py, py, pz * pz));

        int gp = b * Nn + pos_;
        g_AC[gp] = make_float2(A, C);
        g_P[gp]  = make_float4(-2.f * px, -2.f * py, -2.f * pz, sq);
        g_Q[gp]  = make_float4(qx, qy, qz, ph ? kdL : 0.f);
        g_oidx[gp] = j;

        // per-row MLP, gated by node_mask
        float nrm = sqrtf(fmaf(qx, qx, fmaf(qy, qy, qz * qz)));
        float nn = 0.f;
        #pragma unroll 8
        for (int h = 0; h < Hh; h++) {
            float hid = fmaf(nrm, s_l1w[h], s_l1b[h]);
            nn = fmaf(fmaxf(hid, 0.f), s_l2w[h], nn);
        }
        bool node = mask_at(node_mask, b * Nn + j, isB);
        g_nn[gp] = node ? (nn + l2b) : 0.f;
    }

    if (q == 0 && tid == 0) g_npj[b] = npj;
}

// ---------------------------------------------------------------------------
// Main kernel: rows contiguous in reordered space; f32x2-packed row pairs.
// ---------------------------------------------------------------------------
__global__ __launch_bounds__(THREADS, 3)
void attn_kernel(float* __restrict__ out) {
    __shared__ float2 s_AC[Nn];
    __shared__ float4 s_P[Nn];
    __shared__ float4 s_Q[Nn];
    __shared__ float  s_red[WARPS];
    __shared__ float  s_mean[3];
    __shared__ int    s_tk;

    const int b = blockIdx.y;
    const int tid = threadIdx.x;
    const int w = tid >> 5;
    const int lane = tid & 31;

    // preamble: coalesced copy of precomputed batch data
    {
        const float4* gp = (const float4*)&g_P[b * Nn];
        const float4* gq = (const float4*)&g_Q[b * Nn];
        const float4* ga = (const float4*)&g_AC[b * Nn];
        float4* sp = (float4*)s_P;
        float4* sq = (float4*)s_Q;
        float4* sa = (float4*)s_AC;
        #pragma unroll
        for (int i = tid; i < Nn; i += THREADS) { sp[i] = gp[i]; sq[i] = gq[i]; }
        #pragma unroll
        for (int i = tid; i < Nn / 2; i += THREADS) sa[i] = ga[i];
    }
    const int npj = g_npj[b];
    __syncthreads();

    const int rb = blockIdx.x * ROWS_PER_BLOCK;
    const int base = w * RPT;
    const int p0 = rb + base;
    const int cls = (p0 + RPT <= npj) ? 0 : ((p0 >= npj) ? 2 : 1);
    const int njc = (npj + 31) >> 5;

    // packed per-pair row state
    u64c px2[NPAIR], py2[NPAIR], pz2[NPAIR], sq2[NPAIR], nrm2[NPAIR], rg2[NPAIR];
    u64c sum2[NPAIR], cx2[NPAIR], cy2[NPAIR], cz2[NPAIR];
    #pragma unroll
    for (int t = 0; t < NPAIR; t++) {
        int pa = p0 + 2 * t, pb_ = pa + 1;
        float4 Pa = s_P[pa], Pb = s_P[pb_];
        px2[t] = pk2(-0.5f * Pa.x, -0.5f * Pb.x);
        py2[t] = pk2(-0.5f * Pa.y, -0.5f * Pb.y);
        pz2[t] = pk2(-0.5f * Pa.z, -0.5f * Pb.z);
        sq2[t] = pk2(Pa.w, Pb.w);
        float4 Qa = s_Q[pa], Qb = s_Q[pb_];
        float na = sqrtf(fmaf(Qa.x, Qa.x, fmaf(Qa.y, Qa.y, Qa.z * Qa.z)));
        float nb = sqrtf(fmaf(Qb.x, Qb.x, fmaf(Qb.y, Qb.y, Qb.z * Qb.z)));
        nrm2[t] = pk2(na, nb);
        rg2[t] = pk2((pa < npj) ? 1.f : 0.f, (pb_ < npj) ? 1.f : 0.f);
        sum2[t] = 0ull; cx2[t] = 0ull; cy2[t] = 0ull; cz2[t] = 0ull;
    }

    int jj = 0;
    if (cls == 0) {
        #pragma unroll 2
        for (; jj < njc; jj++) {          // distance segment, all rows pharma
            const int j = jj * 32 + lane;
            const float2 AC = s_AC[j];
            const float4 P  = s_P[j];
            const float4 Q  = s_Q[j];
            u64c A2 = pk2(AC.x, AC.x), C2 = pk2(AC.y, AC.y);
            u64c Px2 = pk2(P.x, P.x), Py2 = pk2(P.y, P.y);
            u64c Pz2 = pk2(P.z, P.z), Pw2 = pk2(P.w, P.w);
            u64c Qx2 = pk2(Q.x, Q.x), Qy2 = pk2(Q.y, Q.y), Qz2 = pk2(Q.z, Q.z);
            u64c cb2 = pk2(Q.w, Q.w);
            #pragma unroll
            for (int t = 0; t < NPAIR; t++) {
                u64c tt = fma2_(Pz2, pz2[t], Pw2);
                tt = fma2_(Py2, py2[t], tt);
                tt = fma2_(Px2, px2[t], tt);
                u64c d2 = add2_(sq2[t], tt);
                float da, db; upk2(da, db, d2);
                float ra = sqrtf_(fmaxf(da, 1e-12f));
                float rb_ = sqrtf_(fmaxf(db, 1e-12f));
                u64c s2 = fma2_(nrm2[t], A2, C2);
                s2 = fma2_(cb2, pk2(ra, rb_), s2);
                float sa, sb; upk2(sa, sb, s2);
                u64c e2 = pk2(ex2f_(sa), ex2f_(sb));
                sum2[t] = add2_(sum2[t], e2);
                cx2[t] = fma2_(e2, Qx2, cx2[t]);
                cy2[t] = fma2_(e2, Qy2, cy2[t]);
                cz2[t] = fma2_(e2, Qz2, cz2[t]);
            }
        }
    } else if (cls == 1) {
        #pragma unroll 2
        for (; jj < njc; jj++) {          // mixed warp: per-row gate
            const int j = jj * 32 + lane;
            const float2 AC = s_AC[j];
            const float4 P  = s_P[j];
            const float4 Q  = s_Q[j];
            u64c A2 = pk2(AC.x, AC.x), C2 = pk2(AC.y, AC.y);
            u64c Px2 = pk2(P.x, P.x), Py2 = pk2(P.y, P.y);
            u64c Pz2 = pk2(P.z, P.z), Pw2 = pk2(P.w, P.w);
            u64c Qx2 = pk2(Q.x, Q.x), Qy2 = pk2(Q.y, Q.y), Qz2 = pk2(Q.z, Q.z);
            u64c cb2 = pk2(Q.w, Q.w);
            #pragma unroll
            for (int t = 0; t < NPAIR; t++) {
                u64c tt = fma2_(Pz2, pz2[t], Pw2);
                tt = fma2_(Py2, py2[t], tt);
                tt = fma2_(Px2, px2[t], tt);
                u64c d2 = add2_(sq2[t], tt);
                float da, db; upk2(da, db, d2);
                float ra = sqrtf_(fmaxf(da, 1e-12f));
                float rb_ = sqrtf_(fmaxf(db, 1e-12f));
                u64c cbt = mul2_(cb2, rg2[t]);
                u64c s2 = fma2_(nrm2[t], A2, C2);
                s2 = fma2_(cbt, pk2(ra, rb_), s2);
                float sa, sb; upk2(sa, sb, s2);
                u64c e2 = pk2(ex2f_(sa), ex2f_(sb));
                sum2[t] = add2_(sum2[t], e2);
                cx2[t] = fma2_(e2, Qx2, cx2[t]);
                cy2[t] = fma2_(e2, Qy2, cy2[t]);
                cz2[t] = fma2_(e2, Qz2, cz2[t]);
            }
        }
    }
    #pragma unroll 4
    for (; jj < Nn / 32; jj++) {          // cheap segment
        const int j = jj * 32 + lane;
        const float2 AC = s_AC[j];
        const float4 Q  = s_Q[j];
        u64c A2 = pk2(AC.x, AC.x), C2 = pk2(AC.y, AC.y);
        u64c Qx2 = pk2(Q.x, Q.x), Qy2 = pk2(Q.y, Q.y), Qz2 = pk2(Q.z, Q.z);
        #pragma unroll
        for (int t = 0; t < NPAIR; t++) {
            u64c s2 = fma2_(nrm2[t], A2, C2);
            float sa, sb; upk2(sa, sb, s2);
            u64c e2 = pk2(ex2f_(sa), ex2f_(sb));
            sum2[t] = add2_(sum2[t], e2);
            cx2[t] = fma2_(e2, Qx2, cx2[t]);
            cy2[t] = fma2_(e2, Qy2, cy2[t]);
            cz2[t] = fma2_(e2, Qz2, cz2[t]);
        }
    }

    // unpack accumulators to scalars
    float sum[RPT], cx[RPT], cy[RPT], cz[RPT];
    #pragma unroll
    for (int t = 0; t < NPAIR; t++) {
        upk2(sum[2 * t], sum[2 * t + 1], sum2[t]);
        upk2(cx[2 * t],  cx[2 * t + 1],  cx2[t]);
        upk2(cy[2 * t],  cy[2 * t + 1],  cy2[t]);
        upk2(cz[2 * t],  cz[2 * t + 1],  cz2[t]);
    }

    #pragma unroll
    for (int r = 0; r < RPT; r++) {
        #pragma unroll
        for (int o = 16; o > 0; o >>= 1) {
            sum[r] += __shfl_xor_sync(0xFFFFFFFFu, sum[r], o);
            cx[r]  += __shfl_xor_sync(0xFFFFFFFFu, cx[r], o);
            cy[r]  += __shfl_xor_sync(0xFFFFFFFFu, cy[r], o);
            cz[r]  += __shfl_xor_sync(0xFFFFFFFFu, cz[r], o);
        }
    }

    #pragma unroll
    for (int r = 0; r < RPT; r++) {
        if (lane == r) {
            int pi = p0 + r;
            float4 Q = s_Q[pi];
            float4 P = s_P[pi];
            float nrm = sqrtf(fmaf(Q.x, Q.x, fmaf(Q.y, Q.y, Q.z * Q.z)));
            float S = sum[r], X = cx[r], Y = cy[r], Z = cz[r];
            if (cls != 2) {
                // remove loop's j==i term, add dist-free term (bit-exact redo)
                float rgf = (pi < npj) ? 1.f : 0.f;
                float cbw = Q.w * rgf;
                float pxi = -0.5f * P.x, pyi = -0.5f * P.y, pzi = -0.5f * P.z;
                float e_wrong = pair_term(s_AC[pi], P, cbw, pxi, pyi, pzi, P.w, nrm);
                float e_right = ex2f_(fmaf(nrm, s_AC[pi].x, s_AC[pi].y));
                float d = e_right - e_wrong;
                S += d; X = fmaf(d, Q.x, X); Y = fmaf(d, Q.y, Y); Z = fmaf(d, Q.z, Z);
            }
            int oi = g_oidx[b * Nn + pi];
            int gi = b * Nn + oi;
            float nn = g_nn[b * Nn + pi];     // already node-gated (0 if masked)
            float f = nn / (S * (nrm + 1e-5f));
            out[gi * 3 + 0] = Q.x * X * f;
            out[gi * 3 + 1] = Q.y * Y * f;
            out[gi * 3 + 2] = Q.z * Z * f;
        }
    }

    // fused per-batch mean subtraction (last block of batch)
    __threadfence();
    __syncthreads();
    if (tid == 0) s_tk = atomicAdd(&g_cnt[b], 1);
    __syncthreads();
    if (s_tk == GRIDX - 1) {
        __threadfence();
        float ax = 0.f, ay = 0.f, az = 0.f;
        for (int n = tid; n < Nn; n += THREADS) {
            const float* o = out + ((size_t)b * Nn + n) * 3;
            ax += o[0]; ay += o[1]; az += o[2];
        }
        float* comps[3] = {&ax, &ay, &az};
        #pragma unroll
        for (int c = 0; c < 3; c++) {
            float v = *comps[c];
            #pragma unroll
            for (int o = 16; o > 0; o >>= 1) v += __shfl_xor_sync(0xFFFFFFFFu, v, o);
            if (lane == 0) s_red[w] = v;
            __syncthreads();
            if (tid == 0) {
                float t = 0.f;
                #pragma unroll
                for (int k = 0; k < WARPS; k++) t += s_red[k];
                s_mean[c] = t * (1.f / Nn);
            }
            __syncthreads();
        }
        float mx = s_mean[0], my = s_mean[1], mz = s_mean[2];
        for (int n = tid; n < Nn; n += THREADS) {
            float* o = out + ((size_t)b * Nn + n) * 3;
            o[0] -= mx; o[1] -= my; o[2] -= mz;
        }
        if (tid == 0) atomicExch(&g_cnt[b], 0);
    }
}

extern "C" void kernel_launch(void* const* d_in, const int* in_sizes, int n_in,
                              void* d_out, int out_size) {
    const float* pos       = (const float*)d_in[0];
    const void*  node_mask = d_in[1];
    const float* p         = (const float*)d_in[2];
    const void*  pharma    = d_in[3];
    const float* lin1_w    = (const float*)d_in[4];
    const float* lin1_b    = (const float*)d_in[5];
    const float* lin2_w    = (const float*)d_in[6];
    const float* lin2_b    = (const float*)d_in[7];
    const float* wp        = (const float*)d_in[8];
    const float* bp        = (const float*)d_in[9];
    const float* wd        = (const float*)d_in[10];
    const float* wc        = (const float*)d_in[12];

    dim3 pgrid(Nn / THREADS, Bb);   // (4, 32)
    pre_kernel<<<pgrid, THREADS>>>(pos, node_mask, p, pharma,
                                   lin1_w, lin1_b, lin2_w, lin2_b,
                                   wp, bp, wd, wc);

    dim3 grid(GRIDX, Bb);
    attn_kernel<<<grid, THREADS>>>((float*)d_out);
}